// round 3
// baseline (speedup 1.0000x reference)
#include <cuda_runtime.h>
#include <cuda_bf16.h>

#define LL   512
#define BSZ  32
#define LP1  513
#define ROWF 1539
#define RCA  3.8f

#define DOT(F, px, py, pz) ((F).x * (px) + (F).y * (py) + (F).z * (pz) + (F).w)

// Scratch: Fa (12 floats, 3x4 row-major) + Fb (12 floats) per (b, l)
__device__ float g_F[BSZ * LL * 24];
// Pre-gathered coords: variant v (l mod 4), batch b, plane j (0..2), unit u (0..127)
// g_CU[v][b][j][u] = coords floats [h'(v) + 12u + 4j .. +3] as float4
__device__ __align__(16) float g_CU[4 * BSZ * 3 * 128 * 4];

// Affine 3x4 stored as r[0..8] row-major + t[9..11]. C = A @ B.
__device__ __forceinline__ void compose(const float* __restrict__ A,
                                        const float* __restrict__ B,
                                        float* __restrict__ C) {
#pragma unroll
    for (int i = 0; i < 3; i++) {
        const float a0 = A[i * 3 + 0], a1 = A[i * 3 + 1], a2 = A[i * 3 + 2];
        C[i * 3 + 0] = a0 * B[0] + a1 * B[3] + a2 * B[6];
        C[i * 3 + 1] = a0 * B[1] + a1 * B[4] + a2 * B[7];
        C[i * 3 + 2] = a0 * B[2] + a1 * B[5] + a2 * B[8];
        C[9 + i]     = a0 * B[9] + a1 * B[10] + a2 * B[11] + A[9 + i];
    }
}

// Pre-gather coords into aligned SoA planes for the 4 shift variants.
__global__ __launch_bounds__(384) void prep_kernel(const float* __restrict__ coords) {
    const int b = blockIdx.x;
    const int v = blockIdx.y;
    const int h = v ? (12 - 3 * v) : 0;   // {0,9,6,3}
    const float* C = coords + b * ROWF;
    const int t = threadIdx.x;            // 384 = 3 planes * 128 units
    const int j = t >> 7, u = t & 127;
    const int e = h + 12 * u + 4 * j;
    float4 val;
    val.x = (e + 0 < ROWF) ? C[e + 0] : 0.f;
    val.y = (e + 1 < ROWF) ? C[e + 1] : 0.f;
    val.z = (e + 2 < ROWF) ? C[e + 2] : 0.f;
    val.w = (e + 3 < ROWF) ? C[e + 3] : 0.f;
    ((float4*)g_CU)[((v * BSZ + b) * 3 + j) * 128 + u] = val;
}

// One block per batch. Warp-shuffle inclusive prefix product over L=512,
// then per-l computation of Fa/Fb = Rprev @ (dB @ Minv).
__global__ __launch_bounds__(LL) void scan_kernel(const float* __restrict__ angles) {
    __shared__ float wTot[16][13];
    const int b    = blockIdx.x;
    const int l    = threadIdx.x;
    const int w    = l >> 5;
    const int lane = l & 31;

    const float alpha = angles[(b * 2 + 0) * LL + l];
    const float beta  = angles[(b * 2 + 1) * LL + l];
    float sa, ca, sb, cb;
    sincosf(alpha, &sa, &ca);
    sincosf(beta,  &sb, &cb);

    float M[12];
    M[0] = ca;  M[1] = -sa * cb; M[2] = sa * sb;
    M[3] = sa;  M[4] = ca * cb;  M[5] = -ca * sb;
    M[6] = 0.f; M[7] = sb;       M[8] = cb;
    M[9] = RCA * ca; M[10] = RCA * sa; M[11] = 0.f;

#pragma unroll
    for (int off = 1; off < 32; off <<= 1) {
        float Lf[12];
#pragma unroll
        for (int k = 0; k < 12; k++) Lf[k] = __shfl_up_sync(0xffffffffu, M[k], off);
        if (lane >= off) {
            float T[12];
            compose(Lf, M, T);
#pragma unroll
            for (int k = 0; k < 12; k++) M[k] = T[k];
        }
    }
    if (lane == 31) {
#pragma unroll
        for (int k = 0; k < 12; k++) wTot[w][k] = M[k];
    }
    __syncthreads();

    if (w == 0) {
        float S[12];
        if (lane < 16) {
#pragma unroll
            for (int k = 0; k < 12; k++) S[k] = wTot[lane][k];
        } else {
            S[0] = 1.f; S[1] = 0.f; S[2] = 0.f;
            S[3] = 0.f; S[4] = 1.f; S[5] = 0.f;
            S[6] = 0.f; S[7] = 0.f; S[8] = 1.f;
            S[9] = 0.f; S[10] = 0.f; S[11] = 0.f;
        }
#pragma unroll
        for (int off = 1; off < 16; off <<= 1) {
            float Lf[12];
#pragma unroll
            for (int k = 0; k < 12; k++) Lf[k] = __shfl_up_sync(0xffffffffu, S[k], off);
            if (lane >= off && lane < 16) {
                float T[12];
                compose(Lf, S, T);
#pragma unroll
                for (int k = 0; k < 12; k++) S[k] = T[k];
            }
        }
        if (lane < 16) {
#pragma unroll
            for (int k = 0; k < 12; k++) wTot[lane][k] = S[k];
        }
    }
    __syncthreads();

    float Fin[12];
    if (w > 0) {
        float P[12];
#pragma unroll
        for (int k = 0; k < 12; k++) P[k] = wTot[w - 1][k];
        compose(P, M, Fin);
    } else {
#pragma unroll
        for (int k = 0; k < 12; k++) Fin[k] = M[k];
    }

    float Mp[12];
#pragma unroll
    for (int k = 0; k < 9; k++) Mp[k] = __shfl_up_sync(0xffffffffu, Fin[k], 1);
    if (lane == 0) {
        if (w == 0) {
            Mp[0] = 1.f; Mp[1] = 0.f; Mp[2] = 0.f;
            Mp[3] = 0.f; Mp[4] = 1.f; Mp[5] = 0.f;
            Mp[6] = 0.f; Mp[7] = 0.f; Mp[8] = 1.f;
        } else {
#pragma unroll
            for (int k = 0; k < 9; k++) Mp[k] = wTot[w - 1][k];
        }
    }
    Mp[9] = 0.f; Mp[10] = 0.f; Mp[11] = 0.f;

    float Mi[12];
    Mi[0] = Fin[0]; Mi[1] = Fin[3]; Mi[2] = Fin[6];
    Mi[3] = Fin[1]; Mi[4] = Fin[4]; Mi[5] = Fin[7];
    Mi[6] = Fin[2]; Mi[7] = Fin[5]; Mi[8] = Fin[8];
    Mi[9]  = -(Mi[0] * Fin[9] + Mi[1] * Fin[10] + Mi[2] * Fin[11]);
    Mi[10] = -(Mi[3] * Fin[9] + Mi[4] * Fin[10] + Mi[5] * Fin[11]);
    Mi[11] = -(Mi[6] * Fin[9] + Mi[7] * Fin[10] + Mi[8] * Fin[11]);

    float Da[12];
    Da[0] = -sa; Da[1] = -ca * cb; Da[2] = ca * sb;
    Da[3] = ca;  Da[4] = -sa * cb; Da[5] = sa * sb;
    Da[6] = 0.f; Da[7] = 0.f;      Da[8] = 0.f;
    Da[9] = -RCA * sa; Da[10] = RCA * ca; Da[11] = 0.f;

    float Db[12];
    Db[0] = 0.f; Db[1] = sa * sb;  Db[2] = sa * cb;
    Db[3] = 0.f; Db[4] = -ca * sb; Db[5] = -ca * cb;
    Db[6] = 0.f; Db[7] = cb;       Db[8] = -sb;
    Db[9] = 0.f; Db[10] = 0.f;     Db[11] = 0.f;

    float G[12], Fa[12], Fb[12];
    compose(Da, Mi, G);
    compose(Mp, G, Fa);
    compose(Db, Mi, G);
    compose(Mp, G, Fb);

    float* o = &g_F[(b * LL + l) * 24];
#pragma unroll
    for (int i = 0; i < 3; i++) {
        o[i * 4 + 0] = Fa[i * 3 + 0];
        o[i * 4 + 1] = Fa[i * 3 + 1];
        o[i * 4 + 2] = Fa[i * 3 + 2];
        o[i * 4 + 3] = Fa[9 + i];
        o[12 + i * 4 + 0] = Fb[i * 3 + 0];
        o[12 + i * 4 + 1] = Fb[i * 3 + 1];
        o[12 + i * 4 + 2] = Fb[i * 3 + 2];
        o[12 + i * 4 + 3] = Fb[9 + i];
    }
}

// Barrier-free emit: thread = one 12-float unit (4 points x 3 comps) of one
// output row; 4 l-values per block. All operands register/L1 resident.
__global__ __launch_bounds__(256) void emit_kernel(const float* __restrict__ coords,
                                                   const int* __restrict__ lens,
                                                   float* __restrict__ out) {
    const int b   = blockIdx.y;
    const int l0  = blockIdx.x << 2;
    const int tid = threadIdx.x;
    const int s   = tid >> 7;      // 0: Fa row, 1: Fb row
    const int u   = tid & 127;     // unit within row
    const int len = lens[b];

#pragma unroll 1
    for (int dl = 0; dl < 4; dl++) {
        const int l  = l0 + dl;
        const int v  = l & 3;
        const int h  = v ? (12 - 3 * v) : 0;   // {0,9,6,3}
        const int Uf = (ROWF - h) / 12;        // {128,127,127,128}
        const bool alive = (l < len);
        const float4* Fb4 = (const float4*)&g_F[(b * LL + l) * 24];

        if (u < Uf) {
            const float4 F0 = Fb4[s * 3 + 0];
            const float4 F1 = Fb4[s * 3 + 1];
            const float4 F2 = Fb4[s * 3 + 2];
            const float4* P = (const float4*)g_CU + (size_t)(v * BSZ + b) * 3 * 128 + u;
            const float4 q0 = P[0];
            const float4 q1 = P[128];
            const float4 q2 = P[256];
            const int m0 = h / 3 + 4 * u;
            const bool on0 = alive && (m0     > l) && (m0     <= len);
            const bool on1 = alive && (m0 + 1 > l) && (m0 + 1 <= len);
            const bool on2 = alive && (m0 + 2 > l) && (m0 + 2 <= len);
            const bool on3 = alive && (m0 + 3 > l) && (m0 + 3 <= len);

            float4 o0, o1, o2;
            o0.x = on0 ? DOT(F0, q0.x, q0.y, q0.z) : 0.f;
            o0.y = on0 ? DOT(F1, q0.x, q0.y, q0.z) : 0.f;
            o0.z = on0 ? DOT(F2, q0.x, q0.y, q0.z) : 0.f;
            o0.w = on1 ? DOT(F0, q0.w, q1.x, q1.y) : 0.f;
            o1.x = on1 ? DOT(F1, q0.w, q1.x, q1.y) : 0.f;
            o1.y = on1 ? DOT(F2, q0.w, q1.x, q1.y) : 0.f;
            o1.z = on2 ? DOT(F0, q1.z, q1.w, q2.x) : 0.f;
            o1.w = on2 ? DOT(F1, q1.z, q1.w, q2.x) : 0.f;
            o2.x = on2 ? DOT(F2, q1.z, q1.w, q2.x) : 0.f;
            o2.y = on3 ? DOT(F0, q2.y, q2.z, q2.w) : 0.f;
            o2.z = on3 ? DOT(F1, q2.y, q2.z, q2.w) : 0.f;
            o2.w = on3 ? DOT(F2, q2.y, q2.z, q2.w) : 0.f;

            float* gp = out + ((size_t)(b * 2 + s) * LL + l) * ROWF + h + 12 * u;
            __stcs((float4*)(gp + 0), o0);
            __stcs((float4*)(gp + 4), o1);
            __stcs((float4*)(gp + 8), o2);
        }

        // Scalar cleanup: elements [0,h) and [h+12*Uf, 1539)
        const int nsc = ROWF - 12 * Uf;   // 3 or 15
        if (tid < 2 * nsc) {
            const int row = (tid >= nsc);
            const int jj  = tid - (row ? nsc : 0);
            const int e   = (jj < h) ? jj : (h + 12 * Uf + (jj - h));
            const int m   = e / 3;
            const int c   = e - 3 * m;
            const bool on = alive && (m > l) && (m <= len);
            float val = 0.f;
            if (on) {
                const float4 Fc = Fb4[row * 3 + c];
                const float* Cp = coords + b * ROWF + 3 * m;
                val = Fc.x * Cp[0] + Fc.y * Cp[1] + Fc.z * Cp[2] + Fc.w;
            }
            out[((size_t)(b * 2 + row) * LL + l) * ROWF + e] = val;
        }
    }
}

extern "C" void kernel_launch(void* const* d_in, const int* in_sizes, int n_in,
                              void* d_out, int out_size) {
    const float* angles = (const float*)d_in[0];   // (32, 2, 512)
    const float* coords = (const float*)d_in[1];   // (32, 1539)
    const int*   lens   = (const int*)d_in[2];     // (32,)
    float* out = (float*)d_out;

    prep_kernel<<<dim3(BSZ, 4), 384>>>(coords);
    scan_kernel<<<BSZ, LL>>>(angles);
    emit_kernel<<<dim3(LL / 4, BSZ), 256>>>(coords, lens, out);
}